// round 2
// baseline (speedup 1.0000x reference)
#include <cuda_runtime.h>
#include <math_constants.h>

// Problem constants
constexpr int B_ROWS = 16384;
constexpr int D      = 2048;
constexpr int N_TOP  = 8;
constexpr int N_CLS  = 16;
constexpr int N_OUT  = N_TOP * N_CLS;   // 128
constexpr int NPAD   = 144;             // 8 top + 128 bottom + 8 zero pad

// GEMM tiling
constexpr int BM = 64;
constexpr int BK = 16;
constexpr int TM = 8;
constexpr int TN = 9;
constexpr int THREADS = 128;            // 8 (ty) x 16 (tx)
constexpr int NTILES = D / BK;          // 128

// Epilogue smem row pitch (145 coprime with 32 -> conflict free)
constexpr int LPITCH = 145;

// Packed weights scratch (device globals; no allocation allowed)
__device__ float g_Wc[D * NPAD];
__device__ float g_bc[NPAD];

// ---------------------------------------------------------------------------
// Pack top_W (8,2048) and bottom_W (8,2048,16) into Wc[d][n], n = col:
//   n in [0,8): top logit t=n         -> top_W[n*D + d]
//   n in [8,136): t=(n-8)/16, c=(n-8)%16 -> bottom_W[(t*D + d)*16 + c]
//   n in [136,144): zero pad
// Also pack biases.
// ---------------------------------------------------------------------------
__global__ void pack_weights_kernel(const float* __restrict__ topW,
                                    const float* __restrict__ topb,
                                    const float* __restrict__ botW,
                                    const float* __restrict__ botb) {
    int idx = blockIdx.x * blockDim.x + threadIdx.x;
    if (idx < NPAD) {
        float bv = 0.0f;
        if (idx < N_TOP)           bv = topb[idx];
        else if (idx < 8 + N_OUT)  bv = botb[idx - 8];
        g_bc[idx] = bv;
    }
    if (idx >= D * NPAD) return;
    int d = idx / NPAD;
    int n = idx - d * NPAD;
    float v = 0.0f;
    if (n < N_TOP) {
        v = topW[n * D + d];
    } else if (n < 8 + N_OUT) {
        int m = n - 8;
        int t = m >> 4;
        int c = m & 15;
        v = botW[(t * D + d) * N_CLS + c];
    }
    g_Wc[idx] = v;
}

// ---------------------------------------------------------------------------
// Fused GEMM (64x144 tile per block, fp32, double-buffered smem) + epilogue
// (sigmoid gate * per-group softmax) + coalesced store.
// ---------------------------------------------------------------------------
__global__ __launch_bounds__(THREADS, 2)
void hier_classifier_kernel(const float* __restrict__ A, float* __restrict__ out) {
    // smem: union of {As0,As1,Bs0,Bs1} (6656 floats) and logits (64*145 = 9280)
    __shared__ float smem[BM * LPITCH];
    float* As0 = smem;                  // 64*16 = 1024
    float* As1 = smem + 1024;
    float* Bs0 = smem + 2048;           // 16*144 = 2304
    float* Bs1 = smem + 2048 + 2304;

    const int tid = threadIdx.x;
    const int tx  = tid & 15;   // 0..15 -> col group (9 cols)
    const int ty  = tid >> 4;   // 0..7  -> row group (8 rows)
    const int rowBase = blockIdx.x * BM;

    // A staging: 2 float4 per thread per tile
    const int ar0 = tid >> 2;   // 0..31
    const int aq  = tid & 3;    // quad within BK=16
    const float* Aptr0 = A + (size_t)(rowBase + ar0) * D + aq * 4;
    const float* Aptr1 = A + (size_t)(rowBase + ar0 + 32) * D + aq * 4;

    float acc[TM][TN];
#pragma unroll
    for (int i = 0; i < TM; ++i)
#pragma unroll
        for (int j = 0; j < TN; ++j) acc[i][j] = 0.0f;

    float4 a0, a1;
    float4 bst[5];

    // ---- prologue: load tile 0 into registers ----
    {
        a0 = *reinterpret_cast<const float4*>(Aptr0);
        a1 = *reinterpret_cast<const float4*>(Aptr1);
#pragma unroll
        for (int i = 0; i < 5; ++i) {
            int idx = tid + i * THREADS;      // float4 index into 16x144 tile
            if (idx < (BK * NPAD) / 4) {
                int d = idx / 36;
                int g = idx - d * 36;
                bst[i] = *reinterpret_cast<const float4*>(g_Wc + d * NPAD + g * 4);
            }
        }
    }
    // store tile 0
    {
        reinterpret_cast<float4*>(As0)[ar0 * 4 + aq] = a0;
        reinterpret_cast<float4*>(As0)[(ar0 + 32) * 4 + aq] = a1;
#pragma unroll
        for (int i = 0; i < 5; ++i) {
            int idx = tid + i * THREADS;
            if (idx < (BK * NPAD) / 4) reinterpret_cast<float4*>(Bs0)[idx] = bst[i];
        }
    }
    __syncthreads();

    for (int kt = 0; kt < NTILES; ++kt) {
        float* Asb = (kt & 1) ? As1 : As0;
        float* Bsb = (kt & 1) ? Bs1 : Bs0;
        float* Asn = (kt & 1) ? As0 : As1;
        float* Bsn = (kt & 1) ? Bs0 : Bs1;

        // prefetch next tile into registers (in flight during compute)
        if (kt + 1 < NTILES) {
            int k0 = (kt + 1) * BK;
            a0 = *reinterpret_cast<const float4*>(Aptr0 + k0);
            a1 = *reinterpret_cast<const float4*>(Aptr1 + k0);
#pragma unroll
            for (int i = 0; i < 5; ++i) {
                int idx = tid + i * THREADS;
                if (idx < (BK * NPAD) / 4) {
                    int d = idx / 36;
                    int g = idx - d * 36;
                    bst[i] = *reinterpret_cast<const float4*>(g_Wc + (size_t)(k0 + d) * NPAD + g * 4);
                }
            }
        }

        // compute on current buffers
#pragma unroll
        for (int k = 0; k < BK; ++k) {
            float af[TM], bf[TN];
#pragma unroll
            for (int i = 0; i < TM; ++i) af[i] = Asb[(ty * TM + i) * BK + k];
#pragma unroll
            for (int j = 0; j < TN; ++j) bf[j] = Bsb[k * NPAD + tx * TN + j];
#pragma unroll
            for (int i = 0; i < TM; ++i)
#pragma unroll
                for (int j = 0; j < TN; ++j) acc[i][j] = fmaf(af[i], bf[j], acc[i][j]);
        }

        if (kt + 1 < NTILES) {
            reinterpret_cast<float4*>(Asn)[ar0 * 4 + aq] = a0;
            reinterpret_cast<float4*>(Asn)[(ar0 + 32) * 4 + aq] = a1;
#pragma unroll
            for (int i = 0; i < 5; ++i) {
                int idx = tid + i * THREADS;
                if (idx < (BK * NPAD) / 4) reinterpret_cast<float4*>(Bsn)[idx] = bst[i];
            }
        }
        __syncthreads();
    }

    // ---- epilogue: stage logits (+bias) into smem ----
#pragma unroll
    for (int i = 0; i < TM; ++i) {
        int r = ty * TM + i;
#pragma unroll
        for (int j = 0; j < TN; ++j) {
            int n = tx * TN + j;
            smem[r * LPITCH + n] = acc[i][j] + g_bc[n];
        }
    }
    __syncthreads();

    // one thread per row: sigmoid gate + 8x softmax(16) + combine, in place
    if (tid < BM) {
        float* Lr = smem + tid * LPITCH;
#pragma unroll
        for (int t = 0; t < N_TOP; ++t) {
            float gate = 1.0f / (1.0f + __expf(-Lr[t]));
            float* g = Lr + 8 + t * N_CLS;
            float m = g[0];
#pragma unroll
            for (int c = 1; c < N_CLS; ++c) m = fmaxf(m, g[c]);
            float e[N_CLS];
            float s = 0.0f;
#pragma unroll
            for (int c = 0; c < N_CLS; ++c) { e[c] = __expf(g[c] - m); s += e[c]; }
            float inv = gate / s;
#pragma unroll
            for (int c = 0; c < N_CLS; ++c) g[c] = e[c] * inv;
        }
    }
    __syncthreads();

    // coalesced writeback of the 64x128 result block
    for (int idx = tid; idx < BM * N_OUT; idx += THREADS) {
        int r = idx >> 7;
        int c = idx & 127;
        out[(size_t)(rowBase + r) * N_OUT + c] = smem[r * LPITCH + 8 + c];
    }
}

// ---------------------------------------------------------------------------
// Launch
// ---------------------------------------------------------------------------
extern "C" void kernel_launch(void* const* d_in, const int* in_sizes, int n_in,
                              void* d_out, int out_size) {
    const float* features = (const float*)d_in[0];   // (16384, 2048)
    const float* top_W    = (const float*)d_in[1];   // (8, 2048)
    const float* top_b    = (const float*)d_in[2];   // (8,)
    const float* bottom_W = (const float*)d_in[3];   // (8, 2048, 16)
    const float* bottom_b = (const float*)d_in[4];   // (8, 16)
    float* out = (float*)d_out;                      // (16384, 128)

    {
        int total = D * NPAD;
        int threads = 256;
        int blocks = (total + threads - 1) / threads;
        pack_weights_kernel<<<blocks, threads>>>(top_W, top_b, bottom_W, bottom_b);
    }
    {
        int blocks = B_ROWS / BM;   // 256
        hier_classifier_kernel<<<blocks, THREADS>>>(features, out);
    }
}

// round 4
// speedup vs baseline: 2.3205x; 2.3205x over previous
#include <cuda_runtime.h>
#include <cuda_bf16.h>
#include <cstdint>

// ---------------- problem constants ----------------
constexpr int B_ROWS = 16384;
constexpr int D      = 2048;
constexpr int N_TOP  = 8;
constexpr int N_CLS  = 16;
constexpr int N_OUT  = 128;
constexpr int NC     = 136;          // 8 top + 128 bottom (no pad needed)
constexpr int NTILES = 17;           // 17 x n8 = 136
constexpr int KSTEPS = D / 16;       // 128 k16 steps

constexpr int BM      = 128;
constexpr int THREADS = 512;         // 16 warps: 8 row-groups x 2 col-groups
constexpr int LPITCH  = 137;         // odd -> conflict-free row access

// Packed weights: fragment-layout uint4 {b0hi, b1hi, b0lo, b1lo} per lane.
__device__ uint4 g_Wp[KSTEPS * NTILES * 32];
__device__ float g_bc[NC];

// ---------------- helpers ----------------
__device__ __forceinline__ void split2(float2 v, uint32_t& hi, uint32_t& lo) {
    __nv_bfloat162 h = __float22bfloat162_rn(v);
    float2 hf = __bfloat1622float2(h);
    __nv_bfloat162 l = __float22bfloat162_rn(make_float2(v.x - hf.x, v.y - hf.y));
    hi = *reinterpret_cast<uint32_t*>(&h);
    lo = *reinterpret_cast<uint32_t*>(&l);
}

#define MMA16816(c, a, b0, b1) \
    asm volatile("mma.sync.aligned.m16n8k16.row.col.f32.bf16.bf16.f32 " \
        "{%0,%1,%2,%3}, {%4,%5,%6,%7}, {%8,%9}, {%0,%1,%2,%3};" \
        : "+f"((c)[0]), "+f"((c)[1]), "+f"((c)[2]), "+f"((c)[3]) \
        : "r"((a)[0]), "r"((a)[1]), "r"((a)[2]), "r"((a)[3]), "r"(b0), "r"(b1))

// ---------------------------------------------------------------------------
// Pack W into per-lane fragment layout.
// For mma.m16n8k16 (row.col), B fragment lane l (g=l>>2, q=l&3):
//   b0 = {B[2q][g], B[2q+1][g]},  b1 = {B[2q+8][g], B[2q+9][g]}
// with B[k][n], n = t*8+g (n<8: top_W; 8<=n<136: bottom_W), k = s*16 + ...
// ---------------------------------------------------------------------------
__device__ __forceinline__ float wval(const float* __restrict__ topW,
                                      const float* __restrict__ botW,
                                      int n, int k) {
    if (n < N_TOP) return topW[n * D + k];
    int m = n - 8;
    return botW[((m >> 4) * D + k) * N_CLS + (m & 15)];
}

__global__ void pack_kernel(const float* __restrict__ topW,
                            const float* __restrict__ topb,
                            const float* __restrict__ botW,
                            const float* __restrict__ botb) {
    int idx = blockIdx.x * blockDim.x + threadIdx.x;
    if (idx < NC) g_bc[idx] = (idx < N_TOP) ? topb[idx] : botb[idx - 8];
    if (idx >= KSTEPS * NTILES * 32) return;

    int lane = idx & 31;
    int t    = (idx >> 5) % NTILES;
    int s    = idx / (NTILES * 32);
    int g = lane >> 2, q = lane & 3;
    int n = t * 8 + g;
    int k = s * 16 + 2 * q;

    float x0 = wval(topW, botW, n, k);
    float x1 = wval(topW, botW, n, k + 1);
    float x2 = wval(topW, botW, n, k + 8);
    float x3 = wval(topW, botW, n, k + 9);

    uint32_t h0, l0, h1, l1;
    split2(make_float2(x0, x1), h0, l0);
    split2(make_float2(x2, x3), h1, l1);
    g_Wp[idx] = make_uint4(h0, h1, l0, l1);
}

// ---------------------------------------------------------------------------
// Main fused kernel: split-bf16 HMMA GEMM + gate/softmax epilogue.
// ---------------------------------------------------------------------------
__global__ __launch_bounds__(THREADS, 1)
void hier_mma_kernel(const float* __restrict__ A, float* __restrict__ out) {
    extern __shared__ float L[];            // [128][137]
    const int tid  = threadIdx.x;
    const int lane = tid & 31;
    const int wid  = tid >> 5;
    const int wy   = wid & 7;               // row group (16 rows)
    const int wx   = wid >> 3;              // 0: tiles 0..7, 1: tiles 8..16
    const int g    = lane >> 2;
    const int q    = lane & 3;
    const int rowBase = blockIdx.x * BM;

    const float* a0p = A + (size_t)(rowBase + wy * 16 + g) * D + 2 * q;
    const float* a1p = a0p + 8 * D;
    const int tbase = wx * 8;
    const int nt    = 8 + wx;               // 8 or 9 tiles

    float acc[9][4];
#pragma unroll
    for (int t = 0; t < 9; ++t)
#pragma unroll
        for (int j = 0; j < 4; ++j) acc[t][j] = 0.0f;

#pragma unroll 2
    for (int s = 0; s < KSTEPS; ++s) {
        // A fragments: 4x float2, split to hi/lo bf16 pairs
        float2 x0 = *reinterpret_cast<const float2*>(a0p + s * 16);
        float2 x1 = *reinterpret_cast<const float2*>(a1p + s * 16);
        float2 x2 = *reinterpret_cast<const float2*>(a0p + s * 16 + 8);
        float2 x3 = *reinterpret_cast<const float2*>(a1p + s * 16 + 8);
        uint32_t ahi[4], alo[4];
        split2(x0, ahi[0], alo[0]);
        split2(x1, ahi[1], alo[1]);
        split2(x2, ahi[2], alo[2]);
        split2(x3, ahi[3], alo[3]);

        const uint4* wrow = g_Wp + ((size_t)s * NTILES + tbase) * 32 + lane;
        uint4 b = wrow[0];
#pragma unroll
        for (int tt = 0; tt < 9; ++tt) {
            if (tt < nt) {
                uint4 bn = (tt + 1 < nt) ? wrow[(size_t)(tt + 1) * 32] : b;
                MMA16816(acc[tt], ahi, b.x, b.y);   // Ahi * Whi
                MMA16816(acc[tt], alo, b.x, b.y);   // Alo * Whi
                MMA16816(acc[tt], ahi, b.z, b.w);   // Ahi * Wlo
                b = bn;
            }
        }
    }

    // ---- stage logits (+bias) into smem ----
#pragma unroll
    for (int tt = 0; tt < 9; ++tt) {
        if (tt < nt) {
            int c  = (tbase + tt) * 8 + 2 * q;
            int r  = wy * 16 + g;
            L[r * LPITCH + c]           = acc[tt][0] + g_bc[c];
            L[r * LPITCH + c + 1]       = acc[tt][1] + g_bc[c + 1];
            L[(r + 8) * LPITCH + c]     = acc[tt][2] + g_bc[c];
            L[(r + 8) * LPITCH + c + 1] = acc[tt][3] + g_bc[c + 1];
        }
    }
    __syncthreads();

    // ---- per-row: sigmoid gate + 8x softmax(16), in place ----
    if (tid < BM) {
        float* Lr = L + tid * LPITCH;
#pragma unroll
        for (int t = 0; t < N_TOP; ++t) {
            float gate = 1.0f / (1.0f + __expf(-Lr[t]));
            float* gr = Lr + 8 + t * N_CLS;
            float m = gr[0];
#pragma unroll
            for (int c = 1; c < N_CLS; ++c) m = fmaxf(m, gr[c]);
            float e[N_CLS];
            float sum = 0.0f;
#pragma unroll
            for (int c = 0; c < N_CLS; ++c) { e[c] = __expf(gr[c] - m); sum += e[c]; }
            float inv = gate / sum;
#pragma unroll
            for (int c = 0; c < N_CLS; ++c) gr[c] = e[c] * inv;
        }
    }
    __syncthreads();

    // ---- coalesced writeback 128x128 ----
    for (int idx = tid; idx < BM * N_OUT; idx += THREADS) {
        int r = idx >> 7, c = idx & 127;
        out[(size_t)(rowBase + r) * N_OUT + c] = L[r * LPITCH + 8 + c];
    }
}

// ---------------------------------------------------------------------------
extern "C" void kernel_launch(void* const* d_in, const int* in_sizes, int n_in,
                              void* d_out, int out_size) {
    const float* features = (const float*)d_in[0];
    const float* top_W    = (const float*)d_in[1];
    const float* top_b    = (const float*)d_in[2];
    const float* bottom_W = (const float*)d_in[3];
    const float* bottom_b = (const float*)d_in[4];
    float* out = (float*)d_out;

    {
        int total = KSTEPS * NTILES * 32;
        int threads = 256;
        pack_kernel<<<(total + threads - 1) / threads, threads>>>(
            top_W, top_b, bottom_W, bottom_b);
    }
    constexpr int SMEM = BM * LPITCH * sizeof(float);   // 70144 B
    cudaFuncSetAttribute(hier_mma_kernel,
                         cudaFuncAttributeMaxDynamicSharedMemorySize, SMEM);
    hier_mma_kernel<<<B_ROWS / BM, THREADS, SMEM>>>(features, out);
}